// round 15
// baseline (speedup 1.0000x reference)
#include <cuda_runtime.h>
#include <math.h>

typedef unsigned long long ull;

#define FEAT_DIM 360
#define MAXB     32
#define NT       256
#define TILE     32

__device__ float g_feat[MAXB * FEAT_DIM];

// ---------------- packed f32x2 helpers ----------------
__device__ __forceinline__ ull pack2(float lo, float hi) {
    ull r; asm("mov.b64 %0, {%1, %2};" : "=l"(r) : "f"(lo), "f"(hi)); return r;
}
__device__ __forceinline__ ull fma2(ull a, ull b, ull c) {
    ull r; asm("fma.rn.f32x2 %0, %1, %2, %3;" : "=l"(r) : "l"(a), "l"(b), "l"(c)); return r;
}
__device__ __forceinline__ ull mul2(ull a, ull b) {
    ull r; asm("mul.rn.f32x2 %0, %1, %2;" : "=l"(r) : "l"(a), "l"(b)); return r;
}
__device__ __forceinline__ ull add2(ull a, ull b) {
    ull r; asm("add.rn.f32x2 %0, %1, %2;" : "=l"(r) : "l"(a), "l"(b)); return r;
}
// (hi(a), lo(b)) -- exactly 2 register moves
__device__ __forceinline__ ull mid2(ull a, ull b) {
    ull r;
    asm("{\n\t"
        ".reg .b32 al, ah, bl, bh;\n\t"
        "mov.b64 {al, ah}, %1;\n\t"
        "mov.b64 {bl, bh}, %2;\n\t"
        "mov.b64 %0, {ah, bl};\n\t"
        "}" : "=l"(r) : "l"(a), "l"(b));
    return r;
}
__device__ __forceinline__ unsigned sm32(const void* p) {
    unsigned a;
    asm("{ .reg .u64 t; cvta.to.shared.u64 t, %1; cvt.u32.u64 %0, t; }" : "=r"(a) : "l"(p));
    return a;
}

#define C06P 0x3F19999A3F19999AULL
#define C04P 0x3ECCCCCD3ECCCCCDULL
#define ONE2 0x3F8000003F800000ULL

// lrelu(v) = 0.6*v + 0.4*|v|  (exact), branch-free packed
__device__ __forceinline__ ull lrelu2(ull v) {
    ull a = v & 0x7FFFFFFF7FFFFFFFULL;
    return fma2(a, (ull)C04P, mul2(v, (ull)C06P));
}

// ---------------- merged preamble: mean(thumb) + GEMV ----------------
#define FT 384
__global__ void feat_kernel(const float* __restrict__ thumb,
                            const float* __restrict__ Wm,
                            const float* __restrict__ bm, int HW) {
    int b = blockIdx.x;
    int tid = threadIdx.x;
    __shared__ float red[FT / 32][3];
    __shared__ float m[3];
    const float4* p = (const float4*)(thumb + (size_t)b * 3 * HW);
    int n4c = HW / 4;
    float s[3];
    #pragma unroll
    for (int c = 0; c < 3; c++) {
        float acc = 0.0f;
        for (int i = tid; i < n4c; i += FT) {
            float4 v = p[c * n4c + i];
            acc += (v.x + v.y) + (v.z + v.w);
        }
        s[c] = acc;
    }
    #pragma unroll
    for (int c = 0; c < 3; c++) {
        float v = s[c];
        #pragma unroll
        for (int o = 16; o > 0; o >>= 1) v += __shfl_down_sync(0xffffffffu, v, o);
        if ((tid & 31) == 0) red[tid >> 5][c] = v;
    }
    __syncthreads();
    if (tid == 0) {
        float inv = 1.0f / (float)HW;
        #pragma unroll
        for (int c = 0; c < 3; c++) {
            float t = 0.0f;
            #pragma unroll
            for (int w = 0; w < FT / 32; w++) t += red[w][c];
            m[c] = t * inv;
        }
    }
    __syncthreads();
    if (tid < FEAT_DIM) {
        g_feat[b * FEAT_DIM + tid] =
            m[0] * Wm[tid] + m[1] * Wm[FEAT_DIM + tid] + m[2] * Wm[2 * FEAT_DIM + tid]
            + bm[tid];
    }
}

// ---------------- one 3x3 conv layer on pixel pairs (R10 body) ----------------
template <int S, int D, int SLOTS, bool STORE>
__device__ __forceinline__ void conv3_pairs(const float* __restrict__ src,
                                            float* __restrict__ dst,
                                            const ull* __restrict__ wPack,
                                            int tid, ull outReg[][3]) {
    constexpr int PW = D / 2;
    constexpr int NP = D * PW;
    int off[SLOTS];
    #pragma unroll
    for (int k = 0; k < SLOTS; k++) {
        int p = tid + k * NT;
        int y = p / PW, x = (p - y * PW) * 2;
        off[k] = y * S + x;
    }
    ull acc[SLOTS][3];
    #pragma unroll
    for (int oc = 0; oc < 3; oc++) {
        ull bb = wPack[81 + oc];
        #pragma unroll
        for (int k = 0; k < SLOTS; k++) acc[k][oc] = bb;
    }
    #pragma unroll
    for (int ic = 0; ic < 3; ic++) {
        #pragma unroll
        for (int ky = 0; ky < 3; ky++) {
            ull w00 = wPack[ 0 + ic * 9 + ky * 3 + 0];
            ull w01 = wPack[ 0 + ic * 9 + ky * 3 + 1];
            ull w02 = wPack[ 0 + ic * 9 + ky * 3 + 2];
            ull w10 = wPack[27 + ic * 9 + ky * 3 + 0];
            ull w11 = wPack[27 + ic * 9 + ky * 3 + 1];
            ull w12 = wPack[27 + ic * 9 + ky * 3 + 2];
            ull w20 = wPack[54 + ic * 9 + ky * 3 + 0];
            ull w21 = wPack[54 + ic * 9 + ky * 3 + 1];
            ull w22 = wPack[54 + ic * 9 + ky * 3 + 2];
            #pragma unroll
            for (int k = 0; k < SLOTS; k++) {
                bool active = ((k + 1) * NT <= NP) || (tid + k * NT < NP);
                if (active) {
                    const float* s = src + ic * S * S + ky * S + off[k];
                    ull v0 = *(const ull*)s;
                    ull v2 = *(const ull*)(s + 2);
                    ull v1 = mid2(v0, v2);
                    acc[k][0] = fma2(w00, v0, acc[k][0]);
                    acc[k][1] = fma2(w10, v0, acc[k][1]);
                    acc[k][2] = fma2(w20, v0, acc[k][2]);
                    acc[k][0] = fma2(w01, v1, acc[k][0]);
                    acc[k][1] = fma2(w11, v1, acc[k][1]);
                    acc[k][2] = fma2(w21, v1, acc[k][2]);
                    acc[k][0] = fma2(w02, v2, acc[k][0]);
                    acc[k][1] = fma2(w12, v2, acc[k][1]);
                    acc[k][2] = fma2(w22, v2, acc[k][2]);
                }
            }
        }
    }
    #pragma unroll
    for (int k = 0; k < SLOTS; k++) {
        int p = tid + k * NT;
        bool active = ((k + 1) * NT <= NP) || (p < NP);
        if (active) {
            int y = p / PW, x = (p - y * PW) * 2;
            #pragma unroll
            for (int oc = 0; oc < 3; oc++) {
                ull r = lrelu2(acc[k][oc]);
                if (STORE) *(ull*)(dst + oc * D * D + y * D + x) = r;
                else       outReg[k][oc] = r;
            }
        }
    }
}

// ---------------- tile decode ----------------
struct TileInfo {
    const float* src; float* dst; int H; int y0; int x0; int b;
};
__device__ __forceinline__ TileInfo decode_tile(
    int t, int B, int Hm, int tRowM, int mainTotal,
    const float* xMain, const float* xThumb, float* outAll) {
    TileInfo ti;
    if (t < mainTotal) {
        int per = tRowM * tRowM;
        int b = t / per, tile = t - b * per;
        int ty = tile / tRowM, tx = tile - ty * tRowM;
        ti.b = b; ti.H = Hm; ti.y0 = ty * TILE; ti.x0 = tx * TILE;
        ti.src = xMain + (size_t)b * 3 * Hm * Hm;
        ti.dst = outAll + (size_t)b * 3 * Hm * Hm;
    } else {
        int r = t - mainTotal;
        int b = r >> 2, tile = r & 3;
        ti.b = b; ti.H = 64; ti.y0 = (tile >> 1) * TILE; ti.x0 = (tile & 1) * TILE;
        ti.src = xThumb + (size_t)b * 3 * 64 * 64;
        ti.dst = outAll + (size_t)B * 3 * Hm * Hm + (size_t)b * 3 * 64 * 64;
    }
    return ti;
}

// ---------------- async tile prefetch (gmem -> smem, zfill borders) ----------------
__device__ __forceinline__ void prefetch_tile(float* buf, const TileInfo ti, int tid) {
    for (int i = tid; i < 3 * 1444; i += NT) {
        int c = i / 1444;
        int r = i - c * 1444;
        int y = r / 38, xx = r - y * 38;
        int gy = ti.y0 - 3 + y, gx = ti.x0 - 3 + xx;
        bool ok = (gy >= 0 && gy < ti.H && gx >= 0 && gx < ti.H);
        const float* g = ok ? (ti.src + ((size_t)c * ti.H + gy) * ti.H + gx) : ti.src;
        unsigned ss = ok ? 4u : 0u;
        unsigned sa = sm32(buf + i);
        asm volatile("cp.async.ca.shared.global [%0], [%1], 4, %2;"
                     :: "r"(sa), "l"(g), "r"(ss));
    }
    asm volatile("cp.async.commit_group;" ::: "memory");
}

// dynamic smem (ull units): sPack 360 | A0 2166 | A1 2166 | B 1944 | C 1734
#define SP_A0   360
#define SP_A1   (SP_A0 + 2166)
#define SP_B    (SP_A1 + 2166)
#define SP_C    (SP_B + 1944)
#define SMEM_ULL (SP_C + 1734)
#define SMEM_BYTES (SMEM_ULL * 8)     // 66,960

// ---------------- fused conv stack + attention: 2 tiles per CTA, pipelined ----------------
__global__ __launch_bounds__(NT, 3) void conv_att_kernel(
    const float* __restrict__ xMain, const float* __restrict__ xThumb,
    float* __restrict__ outAll, int Hm, int B, int tRowM, int total) {
    extern __shared__ __align__(16) ull pool[];
    ull*   sPack = pool;
    float* bufB  = (float*)(pool + SP_B);
    float* bufC  = (float*)(pool + SP_C);

    int mainTotal = B * tRowM * tRowM;
    int tid = threadIdx.x;
    int t0 = blockIdx.x * 2;
    bool hasT1 = (t0 + 1) < total;

    // prefetch tile 0 (independent of g_feat -> overlaps feat kernel under PDL)
    TileInfo ti = decode_tile(t0, B, Hm, tRowM, mainTotal, xMain, xThumb, outAll);
    prefetch_tile((float*)(pool + SP_A0), ti, tid);

    // wait for features, splat once (both tiles share the same batch)
    cudaGridDependencySynchronize();
    for (int j = tid; j < FEAT_DIM; j += NT) {
        float f = g_feat[ti.b * FEAT_DIM + j];
        sPack[j] = pack2(f, f);
    }

    // prefetch tile 1 (group 2) while tile 0 computes
    if (hasT1)
        prefetch_tile((float*)(pool + SP_A1),
                      decode_tile(t0 + 1, B, Hm, tRowM, mainTotal, xMain, xThumb, outAll),
                      tid);

    #pragma unroll
    for (int tt = 0; tt < 2; tt++) {
        if (tt == 1) {
            if (!hasT1) break;
            ti = decode_tile(t0 + 1, B, Hm, tRowM, mainTotal, xMain, xThumb, outAll);
            // wait for tile 1's data (all groups drained)
            asm volatile("cp.async.wait_group 0;" ::: "memory");
        } else {
            // wait for tile 0's data; tile 1's prefetch may still be in flight
            if (hasT1) asm volatile("cp.async.wait_group 1;" ::: "memory");
            else       asm volatile("cp.async.wait_group 0;" ::: "memory");
        }
        __syncthreads();   // data + sPack visible; prev tile fully done with B/C/A

        float* bufA = (float*)(pool + (tt == 0 ? SP_A0 : SP_A1));

        // L1: bufA(38) -> bufB(36)
        conv3_pairs<38, 36, 3, true>(bufA, bufB, sPack, tid, (ull(*)[3])nullptr);
        __syncthreads();
        // L2: bufB(36) -> bufC(34)   (bufA stays intact for the residual)
        conv3_pairs<36, 34, 3, true>(bufB, bufC, sPack + 84, tid, (ull(*)[3])nullptr);
        __syncthreads();
        // L3: bufC(34) -> registers (2 pair-slots/thread, exactly 32x32 tile)
        ull cur[2][3];
        conv3_pairs<34, 32, 2, false>(bufC, (float*)nullptr, sPack + 168, tid, cur);

        // 5x conv1x1 (packed, in registers)
        #pragma unroll
        for (int l = 0; l < 5; l++) {
            const ull* wl = sPack + 252 + l * 12;
            ull W0 = wl[0], W1 = wl[1], W2 = wl[2];
            ull W3 = wl[3], W4 = wl[4], W5 = wl[5];
            ull W6 = wl[6], W7 = wl[7], W8 = wl[8];
            ull B0 = wl[9], B1 = wl[10], B2 = wl[11];
            #pragma unroll
            for (int k = 0; k < 2; k++) {
                ull c0 = cur[k][0], c1 = cur[k][1], c2 = cur[k][2];
                ull n0 = fma2(W0, c0, fma2(W1, c1, fma2(W2, c2, B0)));
                ull n1 = fma2(W3, c0, fma2(W4, c1, fma2(W5, c2, B1)));
                ull n2 = fma2(W6, c0, fma2(W7, c1, fma2(W8, c2, B2)));
                cur[k][0] = lrelu2(n0);
                cur[k][1] = lrelu2(n1);
                cur[k][2] = lrelu2(n2);
            }
        }

        // residual (bufA intact) + polynomial attention + store
        float invH = 1.0f / (float)ti.H;
        #pragma unroll
        for (int k = 0; k < 2; k++) {
            int p = tid + k * NT;
            int y = p >> 4, x = (p & 15) * 2;
            int gy = ti.y0 + y, gx = ti.x0 + x;
            float hv = (float)gy * invH;
            ull hP = pack2(hv, hv);
            ull wP = pack2((float)gx * invH, (float)(gx + 1) * invH);
            #pragma unroll
            for (int oc = 0; oc < 3; oc++) {
                const float* q = &bufA[(oc * 38 + 3 + y) * 38 + 2 + x];
                ull e0 = *(const ull*)q;
                ull e1 = *(const ull*)(q + 2);
                ull v = add2(mid2(e0, e1), cur[k][oc]);
                ull att = (ull)ONE2;
                #pragma unroll
                for (int i = 0; i < 4; i++) {
                    const ull* f = sPack + 312 + oc * 16 + i * 4;
                    ull t = fma2(f[0], hP, fma2(f[1], wP, fma2(f[2], v, f[3])));
                    att = mul2(att, t);
                }
                ull r = mul2(v, add2((ull)ONE2, att));
                *(ull*)&ti.dst[((size_t)oc * ti.H + gy) * ti.H + gx] = r;
            }
        }
    }
}

// ---------------- launch ----------------
extern "C" void kernel_launch(void* const* d_in, const int* in_sizes, int n_in,
                              void* d_out, int out_size) {
    const float* x     = (const float*)d_in[0];
    const float* thumb = (const float*)d_in[1];
    const float* Wm    = (const float*)d_in[2];
    const float* bm    = (const float*)d_in[3];
    float* out = (float*)d_out;

    int Ht = 64;
    int B  = in_sizes[1] / (3 * Ht * Ht);
    if (B < 1) B = 1;
    if (B > MAXB) B = MAXB;
    int hw = in_sizes[0] / (3 * B);
    int Hm = (int)(sqrt((double)hw) + 0.5);

    cudaFuncSetAttribute(conv_att_kernel,
                         cudaFuncAttributeMaxDynamicSharedMemorySize, SMEM_BYTES);

    feat_kernel<<<B, FT>>>(thumb, Wm, bm, Ht * Ht);

    int tRowM = Hm / TILE;
    int total = B * tRowM * tRowM + B * 4;
    int grid  = (total + 1) / 2;

    // NOTE: pairing (2t, 2t+1) stays within one batch because per-batch tile
    // counts (tRowM^2 and 4) are even for all supported shapes.
    cudaLaunchConfig_t cfg = {};
    cfg.gridDim = dim3(grid);
    cfg.blockDim = dim3(NT);
    cfg.dynamicSmemBytes = SMEM_BYTES;
    cfg.stream = 0;
    cudaLaunchAttribute attrs[1];
    attrs[0].id = cudaLaunchAttributeProgrammaticStreamSerialization;
    attrs[0].val.programmaticStreamSerializationAllowed = 1;
    cfg.attrs = attrs;
    cfg.numAttrs = 1;
    cudaLaunchKernelEx(&cfg, conv_att_kernel, x, thumb, out, Hm, B, tRowM, total);
}

// round 16
// speedup vs baseline: 1.5550x; 1.5550x over previous
#include <cuda_runtime.h>
#include <math.h>

typedef unsigned long long ull;

#define FEAT_DIM 360
#define MAXB     32
#define NT       256
#define TILE     32

__device__ float g_feat[MAXB * FEAT_DIM];

// ---------------- packed f32x2 helpers ----------------
__device__ __forceinline__ ull pack2(float lo, float hi) {
    ull r; asm("mov.b64 %0, {%1, %2};" : "=l"(r) : "f"(lo), "f"(hi)); return r;
}
__device__ __forceinline__ ull fma2(ull a, ull b, ull c) {
    ull r; asm("fma.rn.f32x2 %0, %1, %2, %3;" : "=l"(r) : "l"(a), "l"(b), "l"(c)); return r;
}
__device__ __forceinline__ ull mul2(ull a, ull b) {
    ull r; asm("mul.rn.f32x2 %0, %1, %2;" : "=l"(r) : "l"(a), "l"(b)); return r;
}
__device__ __forceinline__ ull add2(ull a, ull b) {
    ull r; asm("add.rn.f32x2 %0, %1, %2;" : "=l"(r) : "l"(a), "l"(b)); return r;
}
// (hi(a), lo(b)) -- exactly 2 register moves
__device__ __forceinline__ ull mid2(ull a, ull b) {
    ull r;
    asm("{\n\t"
        ".reg .b32 al, ah, bl, bh;\n\t"
        "mov.b64 {al, ah}, %1;\n\t"
        "mov.b64 {bl, bh}, %2;\n\t"
        "mov.b64 %0, {ah, bl};\n\t"
        "}" : "=l"(r) : "l"(a), "l"(b));
    return r;
}

#define C06P 0x3F19999A3F19999AULL   // (0.6f, 0.6f)
#define C04P 0x3ECCCCCD3ECCCCCDULL   // (0.4f, 0.4f)
#define ONE2 0x3F8000003F800000ULL   // (1.0f, 1.0f)

// lrelu(v) = 0.6*v + 0.4*|v|  (exact), branch-free packed
__device__ __forceinline__ ull lrelu2(ull v) {
    ull a = v & 0x7FFFFFFF7FFFFFFFULL;
    return fma2(a, (ull)C04P, mul2(v, (ull)C06P));
}

// ---------------- merged preamble: mean(thumb) + GEMV, one launch ----------------
#define FT 384
__global__ void feat_kernel(const float* __restrict__ thumb,
                            const float* __restrict__ Wm,
                            const float* __restrict__ bm, int HW) {
    int b = blockIdx.x;
    int tid = threadIdx.x;
    __shared__ float red[FT / 32][3];
    __shared__ float m[3];
    const float4* p = (const float4*)(thumb + (size_t)b * 3 * HW);
    int n4c = HW / 4;
    float s[3];
    #pragma unroll
    for (int c = 0; c < 3; c++) {
        float acc = 0.0f;
        for (int i = tid; i < n4c; i += FT) {
            float4 v = p[c * n4c + i];
            acc += (v.x + v.y) + (v.z + v.w);
        }
        s[c] = acc;
    }
    #pragma unroll
    for (int c = 0; c < 3; c++) {
        float v = s[c];
        #pragma unroll
        for (int o = 16; o > 0; o >>= 1) v += __shfl_down_sync(0xffffffffu, v, o);
        if ((tid & 31) == 0) red[tid >> 5][c] = v;
    }
    __syncthreads();
    if (tid == 0) {
        float inv = 1.0f / (float)HW;
        #pragma unroll
        for (int c = 0; c < 3; c++) {
            float t = 0.0f;
            #pragma unroll
            for (int w = 0; w < FT / 32; w++) t += red[w][c];
            m[c] = t * inv;
        }
    }
    __syncthreads();
    if (tid < FEAT_DIM) {
        g_feat[b * FEAT_DIM + tid] =
            m[0] * Wm[tid] + m[1] * Wm[FEAT_DIM + tid] + m[2] * Wm[2 * FEAT_DIM + tid]
            + bm[tid];
    }
}

// ---------------- one 3x3 conv layer on pixel pairs (R10 body, proven best) ----------------
template <int S, int D, int SLOTS, bool STORE>
__device__ __forceinline__ void conv3_pairs(const float* __restrict__ src,
                                            float* __restrict__ dst,
                                            const ull* __restrict__ wPack,
                                            int tid, ull outReg[][3]) {
    constexpr int PW = D / 2;
    constexpr int NP = D * PW;
    int off[SLOTS];
    #pragma unroll
    for (int k = 0; k < SLOTS; k++) {
        int p = tid + k * NT;
        int y = p / PW, x = (p - y * PW) * 2;
        off[k] = y * S + x;
    }
    ull acc[SLOTS][3];
    #pragma unroll
    for (int oc = 0; oc < 3; oc++) {
        ull bb = wPack[81 + oc];
        #pragma unroll
        for (int k = 0; k < SLOTS; k++) acc[k][oc] = bb;
    }
    #pragma unroll
    for (int ic = 0; ic < 3; ic++) {
        #pragma unroll
        for (int ky = 0; ky < 3; ky++) {
            ull w00 = wPack[ 0 + ic * 9 + ky * 3 + 0];
            ull w01 = wPack[ 0 + ic * 9 + ky * 3 + 1];
            ull w02 = wPack[ 0 + ic * 9 + ky * 3 + 2];
            ull w10 = wPack[27 + ic * 9 + ky * 3 + 0];
            ull w11 = wPack[27 + ic * 9 + ky * 3 + 1];
            ull w12 = wPack[27 + ic * 9 + ky * 3 + 2];
            ull w20 = wPack[54 + ic * 9 + ky * 3 + 0];
            ull w21 = wPack[54 + ic * 9 + ky * 3 + 1];
            ull w22 = wPack[54 + ic * 9 + ky * 3 + 2];
            #pragma unroll
            for (int k = 0; k < SLOTS; k++) {
                bool active = ((k + 1) * NT <= NP) || (tid + k * NT < NP);
                if (active) {
                    const float* s = src + ic * S * S + ky * S + off[k];
                    ull v0 = *(const ull*)s;
                    ull v2 = *(const ull*)(s + 2);
                    ull v1 = mid2(v0, v2);
                    acc[k][0] = fma2(w00, v0, acc[k][0]);
                    acc[k][1] = fma2(w10, v0, acc[k][1]);
                    acc[k][2] = fma2(w20, v0, acc[k][2]);
                    acc[k][0] = fma2(w01, v1, acc[k][0]);
                    acc[k][1] = fma2(w11, v1, acc[k][1]);
                    acc[k][2] = fma2(w21, v1, acc[k][2]);
                    acc[k][0] = fma2(w02, v2, acc[k][0]);
                    acc[k][1] = fma2(w12, v2, acc[k][1]);
                    acc[k][2] = fma2(w22, v2, acc[k][2]);
                }
            }
        }
    }
    #pragma unroll
    for (int k = 0; k < SLOTS; k++) {
        int p = tid + k * NT;
        bool active = ((k + 1) * NT <= NP) || (p < NP);
        if (active) {
            int y = p / PW, x = (p - y * PW) * 2;
            #pragma unroll
            for (int oc = 0; oc < 3; oc++) {
                ull r = lrelu2(acc[k][oc]);
                if (STORE) *(ull*)(dst + oc * D * D + y * D + x) = r;
                else       outReg[k][oc] = r;
            }
        }
    }
}

// ---------------- fused conv stack + attention (main + thumb merged) ----------------
__global__ __launch_bounds__(NT, 3) void conv_att_kernel(
    const float* __restrict__ xMain, const float* __restrict__ xThumb,
    float* __restrict__ outAll, int Hm, int B, int tRowM) {
    __shared__ __align__(16) float bufA[3 * 38 * 38];
    __shared__ __align__(16) float bufB[3 * 36 * 36];
    __shared__ ull sPack[FEAT_DIM];

    int mainTotal = B * tRowM * tRowM;
    int bid = blockIdx.x;
    const float* src; float* dst;
    int H, tRow, b, tile;
    if (bid < mainTotal) {
        int per = tRowM * tRowM;
        b = bid / per; tile = bid - b * per;
        H = Hm; tRow = tRowM;
        src = xMain + (size_t)b * 3 * H * H;
        dst = outAll + (size_t)b * 3 * H * H;
    } else {
        int r = bid - mainTotal;
        b = r >> 2; tile = r & 3;
        H = 64; tRow = 2;
        src = xThumb + (size_t)b * 3 * 64 * 64;
        dst = outAll + (size_t)B * 3 * Hm * Hm + (size_t)b * 3 * 64 * 64;
    }
    int ty = tile / tRow, tx = tile - ty * tRow;
    int y0 = ty * TILE, x0 = tx * TILE;
    int tid = threadIdx.x;

    // load input tile with halo 3 (zero-padded) -- overlaps feat kernel (PDL)
    for (int i = tid; i < 3 * 38 * 38; i += NT) {
        int c = i / 1444;
        int r = i - c * 1444;
        int y = r / 38, xx = r - y * 38;
        int gy = y0 - 3 + y, gx = x0 - 3 + xx;
        float v = 0.0f;
        if (gy >= 0 && gy < H && gx >= 0 && gx < H)
            v = __ldg(&src[((size_t)c * H + gy) * H + gx]);
        bufA[i] = v;
    }

    // wait for feat_kernel's g_feat writes, then splat features
    cudaGridDependencySynchronize();
    for (int j = tid; j < FEAT_DIM; j += NT) {
        float f = g_feat[b * FEAT_DIM + j];
        sPack[j] = pack2(f, f);
    }
    __syncthreads();

    // L1: bufA(38) -> bufB(36)
    conv3_pairs<38, 36, 3, true>(bufA, bufB, sPack, tid, (ull(*)[3])nullptr);

    // stash residual pairs before bufA is reused (aligned loads + mid2)
    ull resP[2][3];
    #pragma unroll
    for (int k = 0; k < 2; k++) {
        int p = tid + k * NT;
        int y = p >> 4, x = (p & 15) * 2;
        #pragma unroll
        for (int oc = 0; oc < 3; oc++) {
            const float* q = &bufA[(oc * 38 + 3 + y) * 38 + 2 + x];
            ull e0 = *(const ull*)q;
            ull e1 = *(const ull*)(q + 2);
            resP[k][oc] = mid2(e0, e1);
        }
    }
    __syncthreads();

    // L2: bufB(36) -> bufA(34)
    conv3_pairs<36, 34, 3, true>(bufB, bufA, sPack + 84, tid, (ull(*)[3])nullptr);
    __syncthreads();

    // L3: bufA(34) -> registers (2 pair-slots/thread, exactly 32x32 tile)
    ull cur[2][3];
    conv3_pairs<34, 32, 2, false>(bufA, (float*)nullptr, sPack + 168, tid, cur);

    // 5x conv1x1 (packed, in registers; weights shared across both pairs)
    #pragma unroll
    for (int l = 0; l < 5; l++) {
        const ull* wl = sPack + 252 + l * 12;
        ull W0 = wl[0], W1 = wl[1], W2 = wl[2];
        ull W3 = wl[3], W4 = wl[4], W5 = wl[5];
        ull W6 = wl[6], W7 = wl[7], W8 = wl[8];
        ull B0 = wl[9], B1 = wl[10], B2 = wl[11];
        #pragma unroll
        for (int k = 0; k < 2; k++) {
            ull c0 = cur[k][0], c1 = cur[k][1], c2 = cur[k][2];
            ull n0 = fma2(W0, c0, fma2(W1, c1, fma2(W2, c2, B0)));
            ull n1 = fma2(W3, c0, fma2(W4, c1, fma2(W5, c2, B1)));
            ull n2 = fma2(W6, c0, fma2(W7, c1, fma2(W8, c2, B2)));
            cur[k][0] = lrelu2(n0);
            cur[k][1] = lrelu2(n1);
            cur[k][2] = lrelu2(n2);
        }
    }
    // residual add
    #pragma unroll
    for (int k = 0; k < 2; k++)
        #pragma unroll
        for (int oc = 0; oc < 3; oc++)
            cur[k][oc] = add2(resP[k][oc], cur[k][oc]);

    // polynomial attention + store -- poly coefficients loaded ONCE for both
    // pair-slots (oc/i outer, k inner): 48 LDS.64 instead of 96.
    {
        float invH = 1.0f / (float)H;
        ull hPk[2], wPk[2];
        int gyk[2], gxk[2];
        #pragma unroll
        for (int k = 0; k < 2; k++) {
            int p = tid + k * NT;
            int y = p >> 4, x = (p & 15) * 2;
            gyk[k] = y0 + y; gxk[k] = x0 + x;
            float hv = (float)gyk[k] * invH;
            hPk[k] = pack2(hv, hv);
            wPk[k] = pack2((float)gxk[k] * invH, (float)(gxk[k] + 1) * invH);
        }
        #pragma unroll
        for (int oc = 0; oc < 3; oc++) {
            ull v0 = cur[0][oc];
            ull v1 = cur[1][oc];
            ull att0 = (ull)ONE2, att1 = (ull)ONE2;
            #pragma unroll
            for (int i = 0; i < 4; i++) {
                const ull* f = sPack + 312 + oc * 16 + i * 4;
                ull F0 = f[0], F1 = f[1], F2 = f[2], F3 = f[3];
                att0 = mul2(att0, fma2(F0, hPk[0], fma2(F1, wPk[0], fma2(F2, v0, F3))));
                att1 = mul2(att1, fma2(F0, hPk[1], fma2(F1, wPk[1], fma2(F2, v1, F3))));
            }
            ull r0 = mul2(v0, add2((ull)ONE2, att0));
            ull r1 = mul2(v1, add2((ull)ONE2, att1));
            *(ull*)&dst[((size_t)oc * H + gyk[0]) * H + gxk[0]] = r0;
            *(ull*)&dst[((size_t)oc * H + gyk[1]) * H + gxk[1]] = r1;
        }
    }
}

// ---------------- launch ----------------
extern "C" void kernel_launch(void* const* d_in, const int* in_sizes, int n_in,
                              void* d_out, int out_size) {
    const float* x     = (const float*)d_in[0];
    const float* thumb = (const float*)d_in[1];
    const float* Wm    = (const float*)d_in[2];
    const float* bm    = (const float*)d_in[3];
    float* out = (float*)d_out;

    int Ht = 64;
    int B  = in_sizes[1] / (3 * Ht * Ht);
    if (B < 1) B = 1;
    if (B > MAXB) B = MAXB;
    int hw = in_sizes[0] / (3 * B);
    int Hm = (int)(sqrt((double)hw) + 0.5);

    feat_kernel<<<B, FT>>>(thumb, Wm, bm, Ht * Ht);

    int tRowM = Hm / TILE;
    int total = B * tRowM * tRowM + B * 4;

    cudaLaunchConfig_t cfg = {};
    cfg.gridDim = dim3(total);
    cfg.blockDim = dim3(NT);
    cfg.dynamicSmemBytes = 0;
    cfg.stream = 0;
    cudaLaunchAttribute attrs[1];
    attrs[0].id = cudaLaunchAttributeProgrammaticStreamSerialization;
    attrs[0].val.programmaticStreamSerializationAllowed = 1;
    cfg.attrs = attrs;
    cfg.numAttrs = 1;
    cudaLaunchKernelEx(&cfg, conv_att_kernel, x, thumb, out, Hm, B, tRowM);
}